// round 8
// baseline (speedup 1.0000x reference)
#include <cuda_runtime.h>

#define B_    16
#define N_    131072
#define TPB   1024
#define PPT   (N_ / TPB)         // 128 points per thread
#define NPT1  1024
#define OUTW  336                // 256 + 64 + 16

// 8 MB static scratch for running min-distances (allocations are forbidden)
__device__ float g_dist[B_][N_];

__device__ __forceinline__ unsigned long long kmax64(unsigned long long a,
                                                     unsigned long long b) {
    return a > b ? a : b;
}

// literal form: ((dx^2 + dy^2) + dz^2), no FMA contraction
__device__ __forceinline__ float sqdist(float xx, float yy, float zz,
                                        float px, float py, float pz) {
    float dx = __fsub_rn(xx, px);
    float dy = __fsub_rn(yy, py);
    float dz = __fsub_rn(zz, pz);
    return __fadd_rn(__fadd_rn(__fmul_rn(dx, dx), __fmul_rn(dy, dy)),
                     __fmul_rn(dz, dz));
}

// One block per batch. Stage 1 (131072 -> 1024) streams from global; the 1024
// selected points accumulate in smem; stages 2-4 run entirely in smem.
// OUTPUT IS WRITTEN AS float32 VALUES OF THE INDICES (dtype hypothesis).
__global__ void __launch_bounds__(TPB, 1)
fps_all(const float* __restrict__ x, float* __restrict__ out) {
    const int b   = blockIdx.x;
    const int tid = threadIdx.x;
    const int lane = tid & 31;
    const int w    = tid >> 5;

    __shared__ float sx[NPT1], sy[NPT1], sz[NPT1], sdist[NPT1];
    __shared__ int   gid[NPT1];
    __shared__ int   sel[256];
    __shared__ float tx[256], ty[256], tz[256];
    __shared__ int   tg[256];
    __shared__ unsigned long long wkey[TPB / 32];
    __shared__ float cp[3];

    const float* xb = x + (size_t)b * (N_ * 3);
    float* db = g_dist[b];
    float* ob = out + b * OUTW;

    // init running distances (re-done every call -> deterministic replays)
    for (int i = tid; i < N_; i += TPB) db[i] = 1e10f;

    if (tid == 0) {
        gid[0] = 0;
        cp[0] = xb[0]; cp[1] = xb[1]; cp[2] = xb[2];
        sx[0] = cp[0]; sy[0] = cp[1]; sz[0] = cp[2];
    }
    __syncthreads();

    // ---------------- stage 1: 1023 iterations over all N points -------------
    for (int it = 0; it < NPT1 - 1; ++it) {
        const float px = cp[0], py = cp[1], pz = cp[2];
        float m = -1.0f;
        int   mi = 0;
#pragma unroll 4
        for (int j = 0; j < PPT; j++) {
            const int p = j * TPB + tid;
            float xx = xb[(size_t)p * 3 + 0];
            float yy = xb[(size_t)p * 3 + 1];
            float zz = xb[(size_t)p * 3 + 2];
            float d  = sqdist(xx, yy, zz, px, py, pz);
            float nd = fminf(db[p], d);
            db[p] = nd;
            if (nd > m) { m = nd; mi = p; }              // strict >: first max
        }
        // key: (dist_bits<<32) | ~idx ; dist>=0 -> bits monotone; ties -> min idx
        unsigned long long key =
            ((unsigned long long)__float_as_uint(m) << 32) | (unsigned)~mi;
#pragma unroll
        for (int o = 16; o; o >>= 1)
            key = kmax64(key, __shfl_xor_sync(0xffffffffu, key, o));
        if (lane == 0) wkey[w] = key;
        __syncthreads();
        if (tid == 0) {
            unsigned long long best = wkey[0];
            for (int k = 1; k < TPB / 32; k++) best = kmax64(best, wkey[k]);
            unsigned widx = (~(unsigned)best) & (N_ - 1);
            gid[it + 1] = (int)widx;
            float wx = xb[(size_t)widx * 3 + 0];
            float wy = xb[(size_t)widx * 3 + 1];
            float wz = xb[(size_t)widx * 3 + 2];
            sx[it + 1] = wx; sy[it + 1] = wy; sz[it + 1] = wz;
            cp[0] = wx; cp[1] = wy; cp[2] = wz;
        }
        __syncthreads();
    }

    // ---------------- stages 2-4: 1024 -> 256 -> 64 -> 16 (all in smem) ------
    int n = NPT1, offs = 0;
    const int cnts[3] = {256, 64, 16};

    for (int st = 0; st < 3; ++st) {
        const int npt = cnts[st];
        for (int i = tid; i < n; i += TPB) sdist[i] = 1e10f;
        if (tid == 0) {
            sel[0] = 0;
            ob[offs] = (float)gid[0];                    // float-encoded index
            cp[0] = sx[0]; cp[1] = sy[0]; cp[2] = sz[0];
        }
        __syncthreads();

        for (int it = 0; it < npt - 1; ++it) {
            const float px = cp[0], py = cp[1], pz = cp[2];
            unsigned long long key = 0ull;
            for (int i = tid; i < n; i += TPB) {
                float d  = sqdist(sx[i], sy[i], sz[i], px, py, pz);
                float nd = fminf(sdist[i], d);
                sdist[i] = nd;
                unsigned long long k =
                    ((unsigned long long)__float_as_uint(nd) << 32) | (unsigned)~i;
                key = kmax64(key, k);
            }
#pragma unroll
            for (int o = 16; o; o >>= 1)
                key = kmax64(key, __shfl_xor_sync(0xffffffffu, key, o));
            if (lane == 0) wkey[w] = key;
            __syncthreads();
            if (tid == 0) {
                unsigned long long best = wkey[0];
                for (int k = 1; k < TPB / 32; k++) best = kmax64(best, wkey[k]);
                unsigned loc = (~(unsigned)best) & (NPT1 - 1);
                sel[it + 1] = (int)loc;
                ob[offs + it + 1] = (float)gid[loc];     // float-encoded index
                cp[0] = sx[loc]; cp[1] = sy[loc]; cp[2] = sz[loc];
            }
            __syncthreads();
        }

        // compact selected points to the front for the next stage
        for (int i = tid; i < npt; i += TPB) {
            int s2 = sel[i];
            tx[i] = sx[s2]; ty[i] = sy[s2]; tz[i] = sz[s2]; tg[i] = gid[s2];
        }
        __syncthreads();
        for (int i = tid; i < npt; i += TPB) {
            sx[i] = tx[i]; sy[i] = ty[i]; sz[i] = tz[i]; gid[i] = tg[i];
        }
        __syncthreads();
        n = npt;
        offs += npt;   // 0 -> 256 -> 320
    }
}

extern "C" void kernel_launch(void* const* d_in, const int* in_sizes, int n_in,
                              void* d_out, int out_size) {
    (void)in_sizes; (void)n_in; (void)out_size;
    const float* x = (const float*)d_in[0];
    float* out = (float*)d_out;
    fps_all<<<B_, TPB>>>(x, out);
}

// round 9
// speedup vs baseline: 4.5090x; 4.5090x over previous
#include <cuda_runtime.h>
#include <cstdint>

#define B_    16
#define N_    131072
#define NB    8                  // CTAs per cluster = slices per batch
#define PPB   (N_ / NB)          // 16384 points per CTA
#define TPB   512
#define PPT   (PPB / TPB)        // 32 points per thread
#define NPT1  1024
#define OUTW  336                // 256 + 64 + 16

// stage-1 winner keys, plain-stored by cluster rank 0 each iteration
__device__ unsigned long long g_key[B_][NPT1];

__device__ __forceinline__ unsigned long long kmax64(unsigned long long a,
                                                     unsigned long long b) {
    return a > b ? a : b;
}

__device__ __forceinline__ unsigned cluster_rank() {
    unsigned r;
    asm("mov.u32 %0, %%cluster_ctarank;" : "=r"(r));
    return r;
}

__device__ __forceinline__ void cluster_sync_() {
    asm volatile("barrier.cluster.arrive.aligned;" ::: "memory");
    asm volatile("barrier.cluster.wait.aligned;" ::: "memory");
}

// store 8B into target cluster CTA's smem at the same offset as local addr
__device__ __forceinline__ void dsmem_st_u64(uint32_t local_smem_addr,
                                             unsigned target_rank,
                                             unsigned long long v) {
    asm volatile(
        "{\n\t"
        ".reg .b32 r;\n\t"
        "mapa.shared::cluster.u32 r, %0, %1;\n\t"
        "st.shared::cluster.b64 [r], %2;\n\t"
        "}"
        :: "r"(local_smem_addr), "r"(target_rank), "l"(v) : "memory");
}

// verified form (rel_err 0.0 in R8): ((dx^2 + dy^2) + dz^2), no contraction
__device__ __forceinline__ float sqdist(float xx, float yy, float zz,
                                        float px, float py, float pz) {
    float dx = __fsub_rn(xx, px);
    float dy = __fsub_rn(yy, py);
    float dz = __fsub_rn(zz, pz);
    return __fadd_rn(__fadd_rn(__fmul_rn(dx, dx), __fmul_rn(dy, dy)),
                     __fmul_rn(dz, dz));
}

// ---------------- stage 1: 131072 -> 1024, one 8-CTA cluster per batch -------
__global__ void __launch_bounds__(TPB, 1) __cluster_dims__(NB, 1, 1)
fps_stage1(const float* __restrict__ x) {
    const unsigned rank = cluster_rank();
    const int b = blockIdx.x / NB;
    extern __shared__ float sxyz[];                       // PPB*3 floats (192 KB)
    __shared__ unsigned long long xkey[2][NB];            // double-buffered exchange
    __shared__ unsigned long long wkey[TPB / 32];

    const float* xb = x + (size_t)b * (N_ * 3);
    const int base = (int)rank * PPB;

    // park slice in SMEM (stride-3 word access: conflict-free, gcd(3,32)=1)
    for (int i = threadIdx.x; i < PPB * 3; i += TPB)
        sxyz[i] = xb[(size_t)base * 3 + i];

    float dist[PPT];
#pragma unroll
    for (int j = 0; j < PPT; j++) dist[j] = 1e10f;

    // first sampled point is global index 0
    float px = xb[0], py = xb[1], pz = xb[2];
    __syncthreads();   // sxyz ready (only this CTA reads it)

    const int lane = threadIdx.x & 31;
    const int w    = threadIdx.x >> 5;
    const uint32_t xka0 = (uint32_t)__cvta_generic_to_shared(&xkey[0][rank]);
    const uint32_t xka1 = (uint32_t)__cvta_generic_to_shared(&xkey[1][rank]);

    for (int it = 0; it < NPT1 - 1; ++it) {
        float m = -1.0f;
        int   mi = 0;
#pragma unroll
        for (int j = 0; j < PPT; j++) {
            const int lp = j * TPB + threadIdx.x;
            float d  = sqdist(sxyz[lp * 3 + 0], sxyz[lp * 3 + 1], sxyz[lp * 3 + 2],
                              px, py, pz);
            float nd = fminf(dist[j], d);
            dist[j] = nd;
            if (nd > m) { m = nd; mi = base + lp; }   // strict >: first max wins
        }
        // key: (dist_bits<<32) | ~idx ; dist>=0 so bits monotone; ties -> min idx
        unsigned long long key =
            ((unsigned long long)__float_as_uint(m) << 32) | (unsigned)~mi;

#pragma unroll
        for (int o = 16; o; o >>= 1)
            key = kmax64(key, __shfl_xor_sync(0xffffffffu, key, o));
        if (lane == 0) wkey[w] = key;
        __syncthreads();

        if (w == 0) {   // reduce 16 warp keys; butterfly gives result to all lanes
            unsigned long long k2 = wkey[lane & 15];
#pragma unroll
            for (int o = 8; o; o >>= 1)
                k2 = kmax64(k2, __shfl_xor_sync(0xffffffffu, k2, o));
            if (lane < NB)   // lane t sends our key to CTA t's xkey[buf][rank]
                dsmem_st_u64((it & 1) ? xka1 : xka0, (unsigned)lane, k2);
        }
        cluster_sync_();   // DSMEM stores visible to all CTAs; also block-syncs

        // every thread reduces the 8 cluster keys (LDS broadcast, cheap)
        unsigned long long best = xkey[it & 1][0];
#pragma unroll
        for (int k = 1; k < NB; k++) best = kmax64(best, xkey[it & 1][k]);
        unsigned widx = (~(unsigned)best) & (N_ - 1);

        if (rank == 0 && threadIdx.x == 0) g_key[b][it] = best;   // plain store

        // winner coords: same addr per warp -> broadcast LDG (L2 hit)
        px = xb[(size_t)widx * 3 + 0];
        py = xb[(size_t)widx * 3 + 1];
        pz = xb[(size_t)widx * 3 + 2];
    }
    cluster_sync_();   // no CTA exits while peers could still be exchanging
}

// ---------------- stages 2-4: 1024 -> 256 -> 64 -> 16 (one block per batch) ---
#define RT 256
__global__ void __launch_bounds__(RT, 1)
fps_rest(const float* __restrict__ x, float* __restrict__ out) {
    const int b = blockIdx.x;
    __shared__ float sx[NPT1], sy[NPT1], sz[NPT1], sdist[NPT1];
    __shared__ int   gid[NPT1];
    __shared__ int   sel[256];
    __shared__ float tx[256], ty[256], tz[256];
    __shared__ int   tg[256];
    __shared__ unsigned long long wkey[RT / 32];
    __shared__ float cp[3];

    const float* xb = x + (size_t)b * (N_ * 3);
    float* ob = out + b * OUTW;
    const int tid = threadIdx.x;

    // decode stage-1 winners (index 0 is the implicit first sample)
    for (int i = tid; i < NPT1; i += RT) {
        unsigned idx = (i == 0) ? 0u : ((~(unsigned)g_key[b][i - 1]) & (N_ - 1));
        gid[i] = (int)idx;
        sx[i] = xb[(size_t)idx * 3 + 0];
        sy[i] = xb[(size_t)idx * 3 + 1];
        sz[i] = xb[(size_t)idx * 3 + 2];
    }
    __syncthreads();

    int n = NPT1, offs = 0;
    const int cnts[3] = {256, 64, 16};

    for (int st = 0; st < 3; ++st) {
        const int npt = cnts[st];
        for (int i = tid; i < n; i += RT) sdist[i] = 1e10f;
        if (tid == 0) {
            sel[0] = 0;
            ob[offs] = (float)gid[0];                 // float32 output (confirmed)
            cp[0] = sx[0]; cp[1] = sy[0]; cp[2] = sz[0];
        }
        __syncthreads();

        for (int it = 0; it < npt - 1; ++it) {
            const float px = cp[0], py = cp[1], pz = cp[2];
            unsigned long long key = 0ull;
            for (int i = tid; i < n; i += RT) {
                float d  = sqdist(sx[i], sy[i], sz[i], px, py, pz);
                float nd = fminf(sdist[i], d);
                sdist[i] = nd;
                unsigned long long k =
                    ((unsigned long long)__float_as_uint(nd) << 32) | (unsigned)~i;
                key = kmax64(key, k);
            }
            const int lane = tid & 31, w = tid >> 5;
#pragma unroll
            for (int o = 16; o; o >>= 1)
                key = kmax64(key, __shfl_xor_sync(0xffffffffu, key, o));
            if (lane == 0) wkey[w] = key;
            __syncthreads();
            if (tid == 0) {
                for (int ww = 1; ww < RT / 32; ww++) key = kmax64(key, wkey[ww]);
                unsigned loc = (~(unsigned)key) & (NPT1 - 1);
                sel[it + 1] = (int)loc;
                ob[offs + it + 1] = (float)gid[loc];  // float32 output
                cp[0] = sx[loc]; cp[1] = sy[loc]; cp[2] = sz[loc];
            }
            __syncthreads();
        }

        // compact the selected npt points to the front for the next stage
        for (int i = tid; i < npt; i += RT) {
            int s2 = sel[i];
            tx[i] = sx[s2]; ty[i] = sy[s2]; tz[i] = sz[s2]; tg[i] = gid[s2];
        }
        __syncthreads();
        for (int i = tid; i < npt; i += RT) {
            sx[i] = tx[i]; sy[i] = ty[i]; sz[i] = tz[i]; gid[i] = tg[i];
        }
        __syncthreads();
        n = npt;
        offs += npt;   // 0 -> 256 -> 320
    }
}

// ---------------- launch ----------------
extern "C" void kernel_launch(void* const* d_in, const int* in_sizes, int n_in,
                              void* d_out, int out_size) {
    (void)in_sizes; (void)n_in; (void)out_size;
    const float* x = (const float*)d_in[0];
    float* out = (float*)d_out;

    cudaFuncSetAttribute(fps_stage1,
                         cudaFuncAttributeMaxDynamicSharedMemorySize,
                         PPB * 3 * sizeof(float));

    fps_stage1<<<B_ * NB, TPB, PPB * 3 * sizeof(float)>>>(x);
    fps_rest<<<B_, RT>>>(x, out);
}

// round 10
// speedup vs baseline: 4.7983x; 1.0642x over previous
#include <cuda_runtime.h>
#include <cstdint>

#define B_    16
#define N_    131072
#define NB    8                  // CTAs per cluster = slices per batch
#define PPB   (N_ / NB)          // 16384 points per CTA
#define TPB   512
#define NPT1  1024
#define OUTW  336                // 256 + 64 + 16

// stage-1 winner keys, plain-stored by cluster rank 0 each iteration
__device__ unsigned long long g_key[B_][NPT1];

__device__ __forceinline__ unsigned long long kmax64(unsigned long long a,
                                                     unsigned long long b) {
    return a > b ? a : b;
}
__device__ __forceinline__ unsigned cluster_rank() {
    unsigned r; asm("mov.u32 %0, %%cluster_ctarank;" : "=r"(r)); return r;
}
__device__ __forceinline__ void cluster_sync_() {
    asm volatile("barrier.cluster.arrive.aligned;" ::: "memory");
    asm volatile("barrier.cluster.wait.aligned;" ::: "memory");
}
__device__ __forceinline__ uint32_t mapa_sh(uint32_t local_addr, unsigned rank) {
    uint32_t r;
    asm("mapa.shared::cluster.u32 %0, %1, %2;" : "=r"(r) : "r"(local_addr), "r"(rank));
    return r;
}
__device__ __forceinline__ void st_cluster_u64(uint32_t addr, unsigned long long v) {
    asm volatile("st.shared::cluster.b64 [%0], %1;" :: "r"(addr), "l"(v) : "memory");
}
__device__ __forceinline__ void st_cluster_u32(uint32_t addr, uint32_t v) {
    asm volatile("st.shared::cluster.b32 [%0], %1;" :: "r"(addr), "r"(v) : "memory");
}
__device__ __forceinline__ void mbar_arrive_rel_cluster(uint32_t mbar_addr) {
    asm volatile("mbarrier.arrive.release.cluster.shared::cluster.b64 _, [%0];"
                 :: "r"(mbar_addr) : "memory");
}
__device__ __forceinline__ void mbar_wait_parity_cluster(uint32_t mbar, uint32_t parity) {
    asm volatile(
        "{\n\t"
        ".reg .pred P;\n\t"
        "W_%=:\n\t"
        "mbarrier.try_wait.parity.acquire.cluster.shared::cta.b64 P, [%0], %1;\n\t"
        "@!P bra W_%=;\n\t"
        "}" :: "r"(mbar), "r"(parity) : "memory");
}

// ---- packed f32x2 helpers (lanes are bit-identical to scalar .rn ops) -------
__device__ __forceinline__ unsigned long long pk2(float lo, float hi) {
    unsigned long long r;
    asm("mov.b64 %0, {%1, %2};" : "=l"(r) : "f"(lo), "f"(hi)); return r;
}
__device__ __forceinline__ void upk2(unsigned long long v, float& lo, float& hi) {
    asm("mov.b64 {%0, %1}, %2;" : "=f"(lo), "=f"(hi) : "l"(v));
}
__device__ __forceinline__ unsigned long long add2(unsigned long long a, unsigned long long b) {
    unsigned long long r;
    asm("add.rn.f32x2 %0, %1, %2;" : "=l"(r) : "l"(a), "l"(b)); return r;
}
__device__ __forceinline__ unsigned long long mul2(unsigned long long a, unsigned long long b) {
    unsigned long long r;
    asm("mul.rn.f32x2 %0, %1, %2;" : "=l"(r) : "l"(a), "l"(b)); return r;
}

// verified scalar form (rel_err 0.0): ((dx^2 + dy^2) + dz^2), no contraction
__device__ __forceinline__ float sqdist(float xx, float yy, float zz,
                                        float px, float py, float pz) {
    float dx = __fsub_rn(xx, px);
    float dy = __fsub_rn(yy, py);
    float dz = __fsub_rn(zz, pz);
    return __fadd_rn(__fadd_rn(__fmul_rn(dx, dx), __fmul_rn(dy, dy)),
                     __fmul_rn(dz, dz));
}

// ---------------- stage 1: 131072 -> 1024, one 8-CTA cluster per batch -------
__global__ void __launch_bounds__(TPB, 1) __cluster_dims__(NB, 1, 1)
fps_stage1(const float* __restrict__ x) {
    const unsigned rank = cluster_rank();
    const int b = blockIdx.x / NB;
    extern __shared__ float smemf[];          // SoA: x | y | z (PPB each, 192 KB)
    float* sxx = smemf;
    float* syy = smemf + PPB;
    float* szz = smemf + 2 * PPB;
    __shared__ unsigned long long xkey[2][NB];     // exchanged keys
    __shared__ unsigned long long xxy[2][NB];      // exchanged (x,y) packed
    __shared__ float xz[2][NB];                    // exchanged z
    __shared__ unsigned long long wkey[2][TPB / 32];
    __shared__ unsigned long long mbar;

    const float* xb = x + (size_t)b * (N_ * 3);
    const int base = (int)rank * PPB;

    // AoS global -> SoA smem (warp covers 384B of x per 32 points: coalesced)
    for (int i = threadIdx.x; i < PPB; i += TPB) {
        const float* p = xb + (size_t)(base + i) * 3;
        sxx[i] = p[0]; syy[i] = p[1]; szz[i] = p[2];
    }

    if (threadIdx.x == 0) {
        asm volatile("mbarrier.init.shared.b64 [%0], %1;"
                     :: "r"((uint32_t)__cvta_generic_to_shared(&mbar)), "r"(NB)
                     : "memory");
    }
    __syncthreads();
    cluster_sync_();   // all mbarriers initialized before any remote arrive

    float dist[32];
#pragma unroll
    for (int j = 0; j < 32; j++) dist[j] = 1e10f;

    // first sampled point is global index 0
    float px = xb[0], py = xb[1], pz = xb[2];

    const int lane = threadIdx.x & 31;
    const int w    = threadIdx.x >> 5;
    const int t4   = threadIdx.x * 4;
    const uint32_t mbar_lcl = (uint32_t)__cvta_generic_to_shared(&mbar);

    for (int it = 0; it < NPT1 - 1; ++it) {
        const int buf = it & 1;
        const unsigned long long npx2 = pk2(-px, -px);
        const unsigned long long npy2 = pk2(-py, -py);
        const unsigned long long npz2 = pk2(-pz, -pz);
        float m = -1.0f;
        int   mi = 0;
#pragma unroll
        for (int j = 0; j < 8; ++j) {
            const int lp = j * (TPB * 4) + t4;           // 4 consecutive points
            float4 xv = *(const float4*)(sxx + lp);
            float4 yv = *(const float4*)(syy + lp);
            float4 zv = *(const float4*)(szz + lp);
            // pair (lp, lp+1)
            unsigned long long dx = add2(pk2(xv.x, xv.y), npx2);
            unsigned long long dy = add2(pk2(yv.x, yv.y), npy2);
            unsigned long long dz = add2(pk2(zv.x, zv.y), npz2);
            unsigned long long ss = add2(add2(mul2(dx, dx), mul2(dy, dy)), mul2(dz, dz));
            float d0, d1; upk2(ss, d0, d1);
            // pair (lp+2, lp+3)
            dx = add2(pk2(xv.z, xv.w), npx2);
            dy = add2(pk2(yv.z, yv.w), npy2);
            dz = add2(pk2(zv.z, zv.w), npz2);
            ss = add2(add2(mul2(dx, dx), mul2(dy, dy)), mul2(dz, dz));
            float d2, d3; upk2(ss, d2, d3);

            const int k = j * 4;
            float nd;
            nd = fminf(dist[k + 0], d0); dist[k + 0] = nd; if (nd > m) { m = nd; mi = lp + 0; }
            nd = fminf(dist[k + 1], d1); dist[k + 1] = nd; if (nd > m) { m = nd; mi = lp + 1; }
            nd = fminf(dist[k + 2], d2); dist[k + 2] = nd; if (nd > m) { m = nd; mi = lp + 2; }
            nd = fminf(dist[k + 3], d3); dist[k + 3] = nd; if (nd > m) { m = nd; mi = lp + 3; }
        }
        // key: (dist_bits<<32) | ~global_idx ; ties -> smallest index
        unsigned long long key =
            ((unsigned long long)__float_as_uint(m) << 32) | (unsigned)~(base + mi);
#pragma unroll
        for (int o = 16; o; o >>= 1)
            key = kmax64(key, __shfl_xor_sync(0xffffffffu, key, o));
        if (lane == 0) wkey[buf][w] = key;
        __syncthreads();                                  // the ONLY block bar/iter

        if (w == 0) {
            // 16 warp keys -> block best in every lane
            unsigned long long k2 = wkey[buf][lane & 15];
#pragma unroll
            for (int o = 8; o; o >>= 1)
                k2 = kmax64(k2, __shfl_xor_sync(0xffffffffu, k2, o));
            // block winner is in OUR slice: read its coords from local SoA
            const int loc = (int)((~(unsigned)k2) & (N_ - 1)) - base;
            const float wxv = sxx[loc], wyv = syy[loc], wzv = szz[loc];
            if (lane < NB) {
                // send (key, x,y, z) to CTA `lane`'s row [rank], then arrive
                const uint32_t ka = mapa_sh((uint32_t)__cvta_generic_to_shared(&xkey[buf][rank]), (unsigned)lane);
                const uint32_t ca = mapa_sh((uint32_t)__cvta_generic_to_shared(&xxy[buf][rank]),  (unsigned)lane);
                const uint32_t za = mapa_sh((uint32_t)__cvta_generic_to_shared(&xz[buf][rank]),   (unsigned)lane);
                st_cluster_u64(ka, k2);
                st_cluster_u64(ca, pk2(wxv, wyv));
                st_cluster_u32(za, __float_as_uint(wzv));
                mbar_arrive_rel_cluster(mapa_sh(mbar_lcl, (unsigned)lane));
            }
        }
        mbar_wait_parity_cluster(mbar_lcl, (uint32_t)buf);   // all 8 arrived

        // every thread reduces the 8 cluster keys + picks winner payload
        unsigned long long best = xkey[buf][0];
        int br = 0;
#pragma unroll
        for (int k = 1; k < NB; k++) {
            unsigned long long v = xkey[buf][k];
            if (v > best) { best = v; br = k; }
        }
        if (rank == 0 && threadIdx.x == 0) g_key[b][it] = best;
        float nx, ny; upk2(xxy[buf][br], nx, ny);
        px = nx; py = ny; pz = xz[buf][br];
    }
    cluster_sync_();   // no CTA exits while peers may still target its smem
}

// ---------------- stages 2-4: 1024 -> 256 -> 64 -> 16 (one block per batch) ---
#define RT 256
__global__ void __launch_bounds__(RT, 1)
fps_rest(const float* __restrict__ x, float* __restrict__ out) {
    const int b = blockIdx.x;
    __shared__ float sx[NPT1], sy[NPT1], sz[NPT1], sdist[NPT1];
    __shared__ int   gid[NPT1];
    __shared__ int   sel[256];
    __shared__ float tx[256], ty[256], tz[256];
    __shared__ int   tg[256];
    __shared__ unsigned long long wkey[2][RT / 32];

    const float* xb = x + (size_t)b * (N_ * 3);
    float* ob = out + b * OUTW;
    const int tid = threadIdx.x;
    const int lane = tid & 31, w = tid >> 5;

    // decode stage-1 winners (index 0 is the implicit first sample)
    for (int i = tid; i < NPT1; i += RT) {
        unsigned idx = (i == 0) ? 0u : ((~(unsigned)g_key[b][i - 1]) & (N_ - 1));
        gid[i] = (int)idx;
        sx[i] = xb[(size_t)idx * 3 + 0];
        sy[i] = xb[(size_t)idx * 3 + 1];
        sz[i] = xb[(size_t)idx * 3 + 2];
    }
    __syncthreads();

    int n = NPT1, offs = 0;
    const int cnts[3] = {256, 64, 16};

    for (int st = 0; st < 3; ++st) {
        const int npt = cnts[st];
        for (int i = tid; i < n; i += RT) sdist[i] = 1e10f;
        if (tid == 0) { sel[0] = 0; ob[offs] = (float)gid[0]; }
        __syncthreads();
        float px = sx[0], py = sy[0], pz = sz[0];

        for (int it = 0; it < npt - 1; ++it) {
            const int buf = it & 1;
            unsigned long long key = 0ull;
            for (int i = tid; i < n; i += RT) {
                float d  = sqdist(sx[i], sy[i], sz[i], px, py, pz);
                float nd = fminf(sdist[i], d);
                sdist[i] = nd;
                unsigned long long k =
                    ((unsigned long long)__float_as_uint(nd) << 32) | (unsigned)~i;
                key = kmax64(key, k);
            }
#pragma unroll
            for (int o = 16; o; o >>= 1)
                key = kmax64(key, __shfl_xor_sync(0xffffffffu, key, o));
            if (lane == 0) wkey[buf][w] = key;
            __syncthreads();                               // only bar per iter
            unsigned long long best = wkey[buf][0];
#pragma unroll
            for (int ww = 1; ww < RT / 32; ww++) best = kmax64(best, wkey[buf][ww]);
            const int loc = (int)((~(unsigned)best) & (NPT1 - 1));
            if (tid == 0) {
                sel[it + 1] = loc;
                ob[offs + it + 1] = (float)gid[loc];       // float32 output
            }
            px = sx[loc]; py = sy[loc]; pz = sz[loc];      // broadcast LDS
        }
        __syncthreads();                                   // sel[] ready

        // compact the selected npt points to the front for the next stage
        for (int i = tid; i < npt; i += RT) {
            int s2 = sel[i];
            tx[i] = sx[s2]; ty[i] = sy[s2]; tz[i] = sz[s2]; tg[i] = gid[s2];
        }
        __syncthreads();
        for (int i = tid; i < npt; i += RT) {
            sx[i] = tx[i]; sy[i] = ty[i]; sz[i] = tz[i]; gid[i] = tg[i];
        }
        __syncthreads();
        n = npt;
        offs += npt;   // 0 -> 256 -> 320
    }
}

// ---------------- launch ----------------
extern "C" void kernel_launch(void* const* d_in, const int* in_sizes, int n_in,
                              void* d_out, int out_size) {
    (void)in_sizes; (void)n_in; (void)out_size;
    const float* x = (const float*)d_in[0];
    float* out = (float*)d_out;

    cudaFuncSetAttribute(fps_stage1,
                         cudaFuncAttributeMaxDynamicSharedMemorySize,
                         PPB * 3 * sizeof(float));

    fps_stage1<<<B_ * NB, TPB, PPB * 3 * sizeof(float)>>>(x);
    fps_rest<<<B_, RT>>>(x, out);
}